// round 5
// baseline (speedup 1.0000x reference)
#include <cuda_runtime.h>
#include <cstdint>

#define BB 128
#define HH 1024
#define LL 256
#define NN 64

// Scratch (device globals: no allocations allowed)
__device__ float g_k[HH * LL];                      // 1 MB  : S4D conv kernel (H,L)
__device__ float g_Wt[2 * HH * HH];                 // 8 MB  : W_out tf32-rounded + quad-permuted
__device__ float g_y[(size_t)BB * HH * LL];         // 128 MB: post-gelu activations (tf32-rounded)

// ---------------------------------------------------------------------------
// helpers
// ---------------------------------------------------------------------------
__device__ __forceinline__ float tf32_round(float f) {
    uint32_t u;
    asm("cvt.rna.tf32.f32 %0, %1;" : "=r"(u) : "f"(f));
    return __uint_as_float(u);
}
__device__ __forceinline__ uint32_t fbits(float f) { return __float_as_uint(f); }

__device__ __forceinline__ void mma_tf32(float c[4], const uint32_t a[4], uint32_t b0, uint32_t b1) {
    asm volatile(
        "mma.sync.aligned.m16n8k8.row.col.f32.tf32.tf32.f32 "
        "{%0,%1,%2,%3}, {%4,%5,%6,%7}, {%8,%9}, {%0,%1,%2,%3};"
        : "+f"(c[0]), "+f"(c[1]), "+f"(c[2]), "+f"(c[3])
        : "r"(a[0]), "r"(a[1]), "r"(a[2]), "r"(a[3]), "r"(b0), "r"(b1));
}

__device__ __forceinline__ float gelu_tanh(float v) {
    float t = tanhf(0.7978845608028654f * (v + 0.044715f * v * v * v));
    return 0.5f * v * (1.0f + t);
}

__device__ __forceinline__ uint32_t smem_u32(const void* p) {
    return (uint32_t)__cvta_generic_to_shared(p);
}
__device__ __forceinline__ void cp_async16(uint32_t dst, const void* src) {
    asm volatile("cp.async.cg.shared.global [%0], [%1], 16;\n" :: "r"(dst), "l"(src));
}
__device__ __forceinline__ void cp_commit() { asm volatile("cp.async.commit_group;\n"); }
__device__ __forceinline__ void cp_wait0() { asm volatile("cp.async.wait_group 0;\n"); }

// ---------------------------------------------------------------------------
// Kernel 1: S4D kernel materialization
// ---------------------------------------------------------------------------
__global__ __launch_bounds__(256) void k_kernel(
    const float* __restrict__ log_dt, const float* __restrict__ A_real_log,
    const float* __restrict__ A_imag, const float* __restrict__ C_re,
    const float* __restrict__ C_im) {
    int h = blockIdx.x;
    __shared__ float sCr[NN], sCi[NN], sAr[NN], sAi[NN];
    int tid = threadIdx.x;
    if (tid < NN) {
        float dt = expf(log_dt[h]);
        float Ar = -expf(A_real_log[h * NN + tid]);
        float Ai = A_imag[h * NN + tid];
        float dAr = Ar * dt, dAi = Ai * dt;
        float er = expf(dAr), sv, cv;
        sincosf(dAi, &sv, &cv);
        float Exr = er * cv - 1.0f;
        float Exi = er * sv;
        float cr = C_re[h * NN + tid], ci = C_im[h * NN + tid];
        float nr = cr * Exr - ci * Exi;
        float ni = cr * Exi + ci * Exr;
        float den = 1.0f / (Ar * Ar + Ai * Ai);
        sCr[tid] = (nr * Ar + ni * Ai) * den;
        sCi[tid] = (ni * Ar - nr * Ai) * den;
        sAr[tid] = dAr;
        sAi[tid] = dAi;
    }
    __syncthreads();
    float l = (float)tid;
    float acc = 0.0f;
#pragma unroll 4
    for (int n = 0; n < NN; n++) {
        float mag = expf(sAr[n] * l);
        float sv, cv;
        sincosf(sAi[n] * l, &sv, &cv);
        acc += sCr[n] * (mag * cv) - sCi[n] * (mag * sv);
    }
    g_k[h * LL + tid] = 2.0f * acc;
}

// ---------------------------------------------------------------------------
// Kernel 2: tf32-round + quad-permute W.
// g_Wt layout: [hb=16][kc=64][R=128][kp=16]
//   R = T*16 + r16, T = wm*2 + half  (source row = hb*64 + wm*16 + r16 + half*1024)
//   kp = q*4 + s*2 + e               (source col = kc*16 + s*8 + q + e*4)
// => one LDS.128 per fragment row yields (a0_s0, a2_s0, a0_s1, a2_s1).
// ---------------------------------------------------------------------------
__global__ __launch_bounds__(256) void wprep_kernel(const float* __restrict__ W) {
    int o = blockIdx.x * 256 + threadIdx.x;
    if (o >= 2 * HH * HH) return;
    int kp = o & 15;
    int R  = (o >> 4) & 127;
    int kc = (o >> 11) & 63;
    int hb = o >> 17;
    int q = kp >> 2, s = (kp >> 1) & 1, e = kp & 1;
    int T = R >> 4, r16 = R & 15;
    int wm = T >> 1, half = T & 1;
    int row = hb * 64 + wm * 16 + r16 + half * HH;
    int col = kc * 16 + s * 8 + q + e * 4;
    g_Wt[o] = tf32_round(W[(size_t)row * HH + col]);
}

// ---------------------------------------------------------------------------
// Kernel 3: causal conv + D-skip + gelu (R3 proven version)
// ---------------------------------------------------------------------------
#define KIDX(i) ((i) + ((i) >> 5))

__global__ __launch_bounds__(256) void conv_kernel(const float* __restrict__ x,
                                                   const float* __restrict__ D) {
    __shared__ float kp[528];
    __shared__ float xs[4][LL];
    int h = blockIdx.x >> 5;
    int b0 = (blockIdx.x & 31) << 2;
    int tid = threadIdx.x;

    kp[KIDX(tid)] = 0.0f;
    kp[KIDX(256 + tid)] = g_k[h * LL + tid];
#pragma unroll
    for (int j = 0; j < 4; j++)
        xs[j][tid] = x[((size_t)(b0 + j) * HH + h) * LL + tid];
    __syncthreads();

    int row = tid >> 6;
    int l0 = (tid & 63) << 2;
    const float* xr = xs[row];
    float Dv = D[h];
    float a0 = Dv * xr[l0 + 0];
    float a1 = Dv * xr[l0 + 1];
    float a2 = Dv * xr[l0 + 2];
    float a3 = Dv * xr[l0 + 3];

    int B0 = 256 + l0;
    float r0 = kp[KIDX(B0 + 0)];
    float r1 = kp[KIDX(B0 + 1)];
    float r2 = kp[KIDX(B0 + 2)];
    float r3 = kp[KIDX(B0 + 3)];

    int lmax = (((tid | 31) & 63) << 2) + 3;

#pragma unroll 4
    for (int s4 = 0; s4 <= lmax; s4 += 4) {
        float x0 = xr[s4 + 0];
        a0 += x0 * r0; a1 += x0 * r1; a2 += x0 * r2; a3 += x0 * r3;
        r3 = kp[KIDX(B0 - s4 - 1)];
        float x1 = xr[s4 + 1];
        a0 += x1 * r3; a1 += x1 * r0; a2 += x1 * r1; a3 += x1 * r2;
        r2 = kp[KIDX(B0 - s4 - 2)];
        float x2 = xr[s4 + 2];
        a0 += x2 * r2; a1 += x2 * r3; a2 += x2 * r0; a3 += x2 * r1;
        r1 = kp[KIDX(B0 - s4 - 3)];
        float x3 = xr[s4 + 3];
        a0 += x3 * r1; a1 += x3 * r2; a2 += x3 * r3; a3 += x3 * r0;
        r0 = kp[KIDX(B0 - s4 - 4)];
    }

    float4 v;
    v.x = tf32_round(gelu_tanh(a0));
    v.y = tf32_round(gelu_tanh(a1));
    v.z = tf32_round(gelu_tanh(a2));
    v.w = tf32_round(gelu_tanh(a3));
    *(float4*)&g_y[((size_t)(b0 + row) * HH + h) * LL + l0] = v;
}

// ---------------------------------------------------------------------------
// Kernel 4: GEMM + GLU (mma.sync tf32, quad-packed fragments).
// Block: 64 h-out (both halves) x 128 l; 8 warps = 4(m) x 2(n), warp m32 x n64.
// A: cp.async from quad-permuted g_Wt, pitch 16 floats; fragments = LDS.128.
// B: LDG->STS k-quad interleaved, pitch 130 float4; fragments = LDS.128.
// Explicit double-buffer unroll (no selects). One barrier per k16 chunk.
// ---------------------------------------------------------------------------
#define A_F4 512                    // 128 rows * 4 float4
#define BQ_PITCH 130                // float4 pitch per quad-row
#define B_F4 (4 * BQ_PITCH)         // 520
#define STAGE_F4 (A_F4 + B_F4)      // 1032 float4 = 16512 B
#define GEMM_SMEM_BYTES (2 * STAGE_F4 * 16)   // 33024 B

__global__ __launch_bounds__(256, 2) void gemm_glu_kernel(const float* __restrict__ bias,
                                                          float* __restrict__ out) {
    extern __shared__ float4 sm4[];

    int lblk = blockIdx.x;          // 0..1  (128 l each)
    int hb   = blockIdx.y;          // 0..15 (64 h each)
    int b    = blockIdx.z;
    int tid = threadIdx.x;
    int lane = tid & 31;
    int wid = tid >> 5;
    int wm = wid & 3;
    int wn = wid >> 2;

    float ca[8][4], cb[8][4];
#pragma unroll
    for (int t = 0; t < 8; t++)
#pragma unroll
        for (int r = 0; r < 4; r++) { ca[t][r] = 0.0f; cb[t][r] = 0.0f; }

    // ---- staging descriptors ----
    const float* aSrc = g_Wt + (size_t)hb * 131072 + tid * 8;      // +=2048 per chunk
    uint32_t aDst0 = smem_u32(sm4 + tid * 2);
    uint32_t aDst1 = aDst0 + STAGE_F4 * 16;

    int sp = tid >> 6;              // quad-row p (0..3)
    int sj = tid & 63;              // covers n pair 2*sj, 2*sj+1
    const float* bS = g_y + (size_t)b * HH * LL + sp * LL + lblk * 128 + sj * 2;  // +=16*LL
    float4* bDst0 = sm4 + A_F4 + sp * BQ_PITCH + sj * 2;
    float4* bDst1 = bDst0 + STAGE_F4;

    // ---- fragment bases ----
    int fr = lane >> 2, q = lane & 3;       // also fc = fr, p = q
    const float4* Arow0 = sm4 + (wm * 32 + fr) * 4 + q;
    const float4* Arow1 = Arow0 + STAGE_F4;
    const float4* Bp0 = sm4 + A_F4 + q * BQ_PITCH + wn * 64 + fr;
    const float4* Bp1 = Bp0 + STAGE_F4;

#define LD_B_REGS(v0, v1, v2, v3) \
    do { v0 = *(const float2*)bS; v1 = *(const float2*)(bS + 4 * LL); \
         v2 = *(const float2*)(bS + 8 * LL); v3 = *(const float2*)(bS + 12 * LL); \
         bS += 16 * LL; } while (0)

#define STS_B(dst, v0, v1, v2, v3) \
    do { dst[0] = make_float4(v0.x, v1.x, v2.x, v3.x); \
         dst[1] = make_float4(v0.y, v1.y, v2.y, v3.y); } while (0)

#define STAGE_A(dst) \
    do { cp_async16(dst, aSrc); cp_async16(dst + 16, aSrc + 4); \
         cp_commit(); aSrc += 2048; } while (0)

#define COMPUTE(Arow, Bp) \
    do { \
        float4 fa0 = Arow[0]; \
        float4 fa1 = Arow[8 * 4]; \
        float4 fb0 = Arow[16 * 4]; \
        float4 fb1 = Arow[24 * 4]; \
        uint32_t aa0[4] = { fbits(fa0.x), fbits(fa1.x), fbits(fa0.y), fbits(fa1.y) }; \
        uint32_t aa1[4] = { fbits(fa0.z), fbits(fa1.z), fbits(fa0.w), fbits(fa1.w) }; \
        uint32_t ab0[4] = { fbits(fb0.x), fbits(fb1.x), fbits(fb0.y), fbits(fb1.y) }; \
        uint32_t ab1[4] = { fbits(fb0.z), fbits(fb1.z), fbits(fb0.w), fbits(fb1.w) }; \
        _Pragma("unroll") \
        for (int t = 0; t < 8; t++) { \
            float4 q4 = Bp[t * 8]; \
            uint32_t b0 = fbits(q4.x), b1 = fbits(q4.y); \
            uint32_t b2 = fbits(q4.z), b3 = fbits(q4.w); \
            mma_tf32(ca[t], aa0, b0, b1); \
            mma_tf32(cb[t], ab0, b0, b1); \
            mma_tf32(ca[t], aa1, b2, b3); \
            mma_tf32(cb[t], ab1, b2, b3); \
        } \
    } while (0)

    // ---- prologue: stage chunk 0 into buf0 ----
    {
        STAGE_A(aDst0);
        float2 v0, v1, v2, v3;
        LD_B_REGS(v0, v1, v2, v3);
        STS_B(bDst0, v0, v1, v2, v3);
        cp_wait0();
        __syncthreads();
    }

#pragma unroll 1
    for (int it = 0; it < 32; it++) {
        // chunk 2it in buf0; prefetch 2it+1 -> buf1 (always exists)
        {
            STAGE_A(aDst1);
            float2 v0, v1, v2, v3;
            LD_B_REGS(v0, v1, v2, v3);
            COMPUTE(Arow0, Bp0);
            STS_B(bDst1, v0, v1, v2, v3);
            cp_wait0();
            __syncthreads();
        }
        // chunk 2it+1 in buf1; prefetch 2it+2 -> buf0 (unless last)
        if (it < 31) {
            STAGE_A(aDst0);
            float2 v0, v1, v2, v3;
            LD_B_REGS(v0, v1, v2, v3);
            COMPUTE(Arow1, Bp1);
            STS_B(bDst0, v0, v1, v2, v3);
            cp_wait0();
            __syncthreads();
        } else {
            COMPUTE(Arow1, Bp1);
        }
    }

    // ---- epilogue: bias + GLU ----
    int r = lane >> 2;
    int c2 = (lane & 3) << 1;
    int h = hb * 64 + wm * 16 + r;
    float ba0 = bias[h],     bb0 = bias[h + HH];
    float ba8 = bias[h + 8], bb8 = bias[h + 8 + HH];
    size_t ob0 = ((size_t)b * HH + h) * LL;
    size_t ob8 = ob0 + (size_t)8 * LL;
#pragma unroll
    for (int t = 0; t < 8; t++) {
        int ll = lblk * 128 + wn * 64 + t * 8 + c2;
        float av, bv;
        float2 w0, w8;
        av = ca[t][0] + ba0; bv = cb[t][0] + bb0;
        w0.x = av * (1.0f / (1.0f + expf(-bv)));
        av = ca[t][1] + ba0; bv = cb[t][1] + bb0;
        w0.y = av * (1.0f / (1.0f + expf(-bv)));
        av = ca[t][2] + ba8; bv = cb[t][2] + bb8;
        w8.x = av * (1.0f / (1.0f + expf(-bv)));
        av = ca[t][3] + ba8; bv = cb[t][3] + bb8;
        w8.y = av * (1.0f / (1.0f + expf(-bv)));
        *(float2*)&out[ob0 + ll] = w0;
        *(float2*)&out[ob8 + ll] = w8;
    }
}

// ---------------------------------------------------------------------------
extern "C" void kernel_launch(void* const* d_in, const int* in_sizes, int n_in,
                              void* d_out, int out_size) {
    const float* x          = (const float*)d_in[0];
    const float* log_dt     = (const float*)d_in[1];
    const float* A_real_log = (const float*)d_in[2];
    const float* A_imag     = (const float*)d_in[3];
    const float* C_re       = (const float*)d_in[4];
    const float* C_im       = (const float*)d_in[5];
    const float* D          = (const float*)d_in[6];
    const float* W_out      = (const float*)d_in[7];
    const float* b_out      = (const float*)d_in[8];
    float* out = (float*)d_out;

    k_kernel<<<HH, 256>>>(log_dt, A_real_log, A_imag, C_re, C_im);
    wprep_kernel<<<(2 * HH * HH) / 256, 256>>>(W_out);
    conv_kernel<<<HH * (BB / 4), 256>>>(x, D);
    gemm_glu_kernel<<<dim3(2, 16, BB), 256, GEMM_SMEM_BYTES>>>(b_out, out);
}

// round 6
// speedup vs baseline: 1.4699x; 1.4699x over previous
#include <cuda_runtime.h>
#include <cuda_fp16.h>
#include <cstdint>

#define BB 128
#define HH 1024
#define LL 256
#define NN 64

// Scratch (device globals: no allocations allowed)
__device__ float  g_k[HH * LL];                       // 1 MB : S4D conv kernel (H,L)
__device__ __half g_Wh[2 * HH * HH];                  // 4 MB : W_out in fp16
__device__ __half g_yh[(size_t)BB * HH * LL];         // 64 MB: post-gelu activations fp16 [b][h][l]

// ---------------------------------------------------------------------------
// helpers
// ---------------------------------------------------------------------------
__device__ __forceinline__ float gelu_tanh(float v) {
    float t = tanhf(0.7978845608028654f * (v + 0.044715f * v * v * v));
    return 0.5f * v * (1.0f + t);
}
__device__ __forceinline__ uint32_t smem_u32(const void* p) {
    return (uint32_t)__cvta_generic_to_shared(p);
}
__device__ __forceinline__ void cp_async16(uint32_t dst, const void* src) {
    asm volatile("cp.async.cg.shared.global [%0], [%1], 16;\n" :: "r"(dst), "l"(src));
}
__device__ __forceinline__ void cp_commit() { asm volatile("cp.async.commit_group;\n"); }
__device__ __forceinline__ void cp_wait0() { asm volatile("cp.async.wait_group 0;\n"); }

__device__ __forceinline__ void mma_f16(float c[4], const uint32_t a[4],
                                        uint32_t b0, uint32_t b1) {
    asm volatile(
        "mma.sync.aligned.m16n8k16.row.col.f32.f16.f16.f32 "
        "{%0,%1,%2,%3}, {%4,%5,%6,%7}, {%8,%9}, {%0,%1,%2,%3};"
        : "+f"(c[0]), "+f"(c[1]), "+f"(c[2]), "+f"(c[3])
        : "r"(a[0]), "r"(a[1]), "r"(a[2]), "r"(a[3]), "r"(b0), "r"(b1));
}

#define LDM_X4(r0, r1, r2, r3, addr) \
    asm volatile("ldmatrix.sync.aligned.m8n8.x4.shared.b16 {%0,%1,%2,%3}, [%4];" \
                 : "=r"(r0), "=r"(r1), "=r"(r2), "=r"(r3) : "r"(addr))
#define LDM_X4T(r0, r1, r2, r3, addr) \
    asm volatile("ldmatrix.sync.aligned.m8n8.x4.trans.shared.b16 {%0,%1,%2,%3}, [%4];" \
                 : "=r"(r0), "=r"(r1), "=r"(r2), "=r"(r3) : "r"(addr))

// ---------------------------------------------------------------------------
// Kernel 1: S4D kernel materialization
// ---------------------------------------------------------------------------
__global__ __launch_bounds__(256) void k_kernel(
    const float* __restrict__ log_dt, const float* __restrict__ A_real_log,
    const float* __restrict__ A_imag, const float* __restrict__ C_re,
    const float* __restrict__ C_im) {
    int h = blockIdx.x;
    __shared__ float sCr[NN], sCi[NN], sAr[NN], sAi[NN];
    int tid = threadIdx.x;
    if (tid < NN) {
        float dt = expf(log_dt[h]);
        float Ar = -expf(A_real_log[h * NN + tid]);
        float Ai = A_imag[h * NN + tid];
        float dAr = Ar * dt, dAi = Ai * dt;
        float er = expf(dAr), sv, cv;
        sincosf(dAi, &sv, &cv);
        float Exr = er * cv - 1.0f;
        float Exi = er * sv;
        float cr = C_re[h * NN + tid], ci = C_im[h * NN + tid];
        float nr = cr * Exr - ci * Exi;
        float ni = cr * Exi + ci * Exr;
        float den = 1.0f / (Ar * Ar + Ai * Ai);
        sCr[tid] = (nr * Ar + ni * Ai) * den;
        sCi[tid] = (ni * Ar - nr * Ai) * den;
        sAr[tid] = dAr;
        sAi[tid] = dAi;
    }
    __syncthreads();
    float l = (float)tid;
    float acc = 0.0f;
#pragma unroll 4
    for (int n = 0; n < NN; n++) {
        float mag = expf(sAr[n] * l);
        float sv, cv;
        sincosf(sAi[n] * l, &sv, &cv);
        acc += sCr[n] * (mag * cv) - sCi[n] * (mag * sv);
    }
    g_k[h * LL + tid] = 2.0f * acc;
}

// ---------------------------------------------------------------------------
// Kernel 2: fp16-cast W (row-major)
// ---------------------------------------------------------------------------
__global__ __launch_bounds__(256) void wprep_kernel(const float* __restrict__ W) {
    int i = (blockIdx.x * 256 + threadIdx.x) * 4;
    if (i >= 2 * HH * HH) return;
    float4 v = *(const float4*)&W[i];
    union { __half2 h[2]; uint2 u; } c;
    c.h[0] = __floats2half2_rn(v.x, v.y);
    c.h[1] = __floats2half2_rn(v.z, v.w);
    *(uint2*)&g_Wh[i] = c.u;
}

// ---------------------------------------------------------------------------
// Kernel 3: causal conv + D-skip + gelu -> fp16 y[b][h][l]
// ---------------------------------------------------------------------------
#define KIDX(i) ((i) + ((i) >> 5))

__global__ __launch_bounds__(256) void conv_kernel(const float* __restrict__ x,
                                                   const float* __restrict__ D) {
    __shared__ float kp[528];
    __shared__ float xs[4][LL];
    int h = blockIdx.x >> 5;
    int b0 = (blockIdx.x & 31) << 2;
    int tid = threadIdx.x;

    kp[KIDX(tid)] = 0.0f;
    kp[KIDX(256 + tid)] = g_k[h * LL + tid];
#pragma unroll
    for (int j = 0; j < 4; j++)
        xs[j][tid] = x[((size_t)(b0 + j) * HH + h) * LL + tid];
    __syncthreads();

    int row = tid >> 6;
    int l0 = (tid & 63) << 2;
    const float* xr = xs[row];
    float Dv = D[h];
    float a0 = Dv * xr[l0 + 0];
    float a1 = Dv * xr[l0 + 1];
    float a2 = Dv * xr[l0 + 2];
    float a3 = Dv * xr[l0 + 3];

    int B0 = 256 + l0;
    float r0 = kp[KIDX(B0 + 0)];
    float r1 = kp[KIDX(B0 + 1)];
    float r2 = kp[KIDX(B0 + 2)];
    float r3 = kp[KIDX(B0 + 3)];

    int lmax = (((tid | 31) & 63) << 2) + 3;

#pragma unroll 4
    for (int s4 = 0; s4 <= lmax; s4 += 4) {
        float x0 = xr[s4 + 0];
        a0 += x0 * r0; a1 += x0 * r1; a2 += x0 * r2; a3 += x0 * r3;
        r3 = kp[KIDX(B0 - s4 - 1)];
        float x1 = xr[s4 + 1];
        a0 += x1 * r3; a1 += x1 * r0; a2 += x1 * r1; a3 += x1 * r2;
        r2 = kp[KIDX(B0 - s4 - 2)];
        float x2 = xr[s4 + 2];
        a0 += x2 * r2; a1 += x2 * r3; a2 += x2 * r0; a3 += x2 * r1;
        r1 = kp[KIDX(B0 - s4 - 3)];
        float x3 = xr[s4 + 3];
        a0 += x3 * r1; a1 += x3 * r2; a2 += x3 * r3; a3 += x3 * r0;
        r0 = kp[KIDX(B0 - s4 - 4)];
    }

    union { __half2 h[2]; uint2 u; } c;
    c.h[0] = __floats2half2_rn(gelu_tanh(a0), gelu_tanh(a1));
    c.h[1] = __floats2half2_rn(gelu_tanh(a2), gelu_tanh(a3));
    *(uint2*)&g_yh[((size_t)(b0 + row) * HH + h) * LL + l0] = c.u;
}

// ---------------------------------------------------------------------------
// Kernel 4: fp16 GEMM + GLU (mma.sync m16n8k16 + ldmatrix).
// Block: 64 h-out (both GLU halves) x 128 l; 8 warps = 4(m) x 2(n);
// warp tile m32 (16 a-rows + 16 b-rows) x n64. K chunks of 32, double-buffered
// cp.async staging for A (W rows) and B (y rows, k-major -> ldmatrix.trans).
// A smem [128][40] halfs, B smem [32][136] halfs: conflict-free ldmatrix.
// ---------------------------------------------------------------------------
#define AP 40
#define BP 136
#define A_H (128 * AP)                 // 5120 halfs
#define B_H (32 * BP)                  // 4352 halfs
#define ST_H (A_H + B_H)               // 9472 halfs = 18944 B
#define ST_B (ST_H * 2)                // stage bytes
#define GEMM_SMEM_BYTES (2 * ST_B)     // 37888 B

__global__ __launch_bounds__(256, 2) void gemm_glu_kernel(const float* __restrict__ bias,
                                                          float* __restrict__ out) {
    extern __shared__ __half smh[];

    int lblk = blockIdx.x;          // 0..1   (128 l each)
    int hb   = blockIdx.y;          // 0..15  (64 h each)
    int b    = blockIdx.z;
    int tid = threadIdx.x;
    int lane = tid & 31;
    int wid = tid >> 5;
    int wm = wid & 3;
    int wn = wid >> 2;

    float ca[8][4], cb[8][4];
#pragma unroll
    for (int t = 0; t < 8; t++)
#pragma unroll
        for (int r = 0; r < 4; r++) { ca[t][r] = 0.0f; cb[t][r] = 0.0f; }

    // ---- staging descriptors ----
    int arow = tid >> 1, aseg2 = (tid & 1) * 2;     // A: row, segments aseg2, aseg2+1
    int wrow = (arow < 64) ? (hb * 64 + arow) : (960 + hb * 64 + arow);
    const __half* aS = g_Wh + (size_t)wrow * HH + aseg2 * 8;        // += 32/chunk
    uint32_t aD = smem_u32(smh + arow * AP + aseg2 * 8);

    int brow = tid >> 3, bs2 = (tid & 7) * 2;       // B: k-row, segments bs2, bs2+1
    const __half* bS = g_yh + (size_t)b * HH * LL + (size_t)brow * LL
                       + lblk * 128 + bs2 * 8;                      // += 32*LL/chunk
    uint32_t bD = smem_u32(smh + A_H + brow * BP + bs2 * 8);

#define STAGE(off) do { \
        cp_async16(aD + (off), aS); cp_async16(aD + (off) + 16, aS + 8); \
        cp_async16(bD + (off), bS); cp_async16(bD + (off) + 16, bS + 8); \
        cp_commit(); aS += 32; bS += 32 * LL; } while (0)

    // ---- fragment smem addresses ----
    int lm = lane & 15, lh = lane >> 4;
    uint32_t aAddrA = smem_u32(smh + (wm * 16 + lm) * AP + lh * 8);
    uint32_t aAddrB = aAddrA + 64 * AP * 2;
    uint32_t bAddr  = smem_u32(smh + A_H + lm * BP + wn * 64 + lh * 8);

#define COMPUTE(off) do { \
        _Pragma("unroll") \
        for (int s = 0; s < 2; s++) { \
            uint32_t aa[4], ab[4]; \
            LDM_X4(aa[0], aa[1], aa[2], aa[3], aAddrA + (off) + s * 32); \
            LDM_X4(ab[0], ab[1], ab[2], ab[3], aAddrB + (off) + s * 32); \
            _Pragma("unroll") \
            for (int p = 0; p < 4; p++) { \
                uint32_t b0, b1, b2, b3; \
                LDM_X4T(b0, b1, b2, b3, bAddr + (off) + s * (16 * BP * 2) + p * 32); \
                mma_f16(ca[2 * p],     aa, b0, b1); \
                mma_f16(ca[2 * p + 1], aa, b2, b3); \
                mma_f16(cb[2 * p],     ab, b0, b1); \
                mma_f16(cb[2 * p + 1], ab, b2, b3); \
            } \
        } } while (0)

    // ---- pipeline: 32 k-chunks, double buffered ----
    STAGE(0);
    cp_wait0();
    __syncthreads();

#pragma unroll 1
    for (int it = 0; it < 16; it++) {
        STAGE(ST_B);            // chunk 2it+1 -> buf1
        COMPUTE(0);             // chunk 2it from buf0
        cp_wait0();
        __syncthreads();
        if (it < 15) {
            STAGE(0);           // chunk 2it+2 -> buf0
            COMPUTE(ST_B);      // chunk 2it+1 from buf1
            cp_wait0();
            __syncthreads();
        } else {
            COMPUTE(ST_B);
        }
    }

    // ---- epilogue: bias + GLU ----
    int r = lane >> 2;
    int c2 = (lane & 3) << 1;
    int h = hb * 64 + wm * 16 + r;
    float ba0 = bias[h],     bb0 = bias[h + HH];
    float ba8 = bias[h + 8], bb8 = bias[h + 8 + HH];
    size_t ob0 = ((size_t)b * HH + h) * LL;
    size_t ob8 = ob0 + (size_t)8 * LL;
#pragma unroll
    for (int t = 0; t < 8; t++) {
        int ll = lblk * 128 + wn * 64 + t * 8 + c2;
        float av, bv;
        float2 w0, w8;
        av = ca[t][0] + ba0; bv = cb[t][0] + bb0;
        w0.x = av * (1.0f / (1.0f + expf(-bv)));
        av = ca[t][1] + ba0; bv = cb[t][1] + bb0;
        w0.y = av * (1.0f / (1.0f + expf(-bv)));
        av = ca[t][2] + ba8; bv = cb[t][2] + bb8;
        w8.x = av * (1.0f / (1.0f + expf(-bv)));
        av = ca[t][3] + ba8; bv = cb[t][3] + bb8;
        w8.y = av * (1.0f / (1.0f + expf(-bv)));
        *(float2*)&out[ob0 + ll] = w0;
        *(float2*)&out[ob8 + ll] = w8;
    }
}

// ---------------------------------------------------------------------------
extern "C" void kernel_launch(void* const* d_in, const int* in_sizes, int n_in,
                              void* d_out, int out_size) {
    const float* x          = (const float*)d_in[0];
    const float* log_dt     = (const float*)d_in[1];
    const float* A_real_log = (const float*)d_in[2];
    const float* A_imag     = (const float*)d_in[3];
    const float* C_re       = (const float*)d_in[4];
    const float* C_im       = (const float*)d_in[5];
    const float* D          = (const float*)d_in[6];
    const float* W_out      = (const float*)d_in[7];
    const float* b_out      = (const float*)d_in[8];
    float* out = (float*)d_out;

    k_kernel<<<HH, 256>>>(log_dt, A_real_log, A_imag, C_re, C_im);
    wprep_kernel<<<(2 * HH * HH) / 1024, 256>>>(W_out);
    conv_kernel<<<HH * (BB / 4), 256>>>(x, D);
    gemm_glu_kernel<<<dim3(2, 16, BB), 256, GEMM_SMEM_BYTES>>>(b_out, out);
}

// round 10
// speedup vs baseline: 2.0708x; 1.4088x over previous
#include <cuda_runtime.h>
#include <cuda_fp16.h>
#include <cstdint>

#define BB 128
#define HH 1024
#define LL 256
#define NN 64

// Scratch (device globals: no allocations allowed)
__device__ float  g_k[HH * LL];                       // 1 MB : S4D conv kernel (H,L) fp32
__device__ __half g_Wh[2 * HH * HH];                  // 4 MB : W_out fp16
__device__ __half g_xh[(size_t)BB * HH * LL];         // 64 MB: x in fp16 [b][h][l]
__device__ __half g_yh[(size_t)BB * HH * LL];         // 64 MB: post-gelu activations fp16 [b][h][l]

// ---------------------------------------------------------------------------
// helpers
// ---------------------------------------------------------------------------
__device__ __forceinline__ float gelu_tanh(float v) {
    float t = tanhf(0.7978845608028654f * (v + 0.044715f * v * v * v));
    return 0.5f * v * (1.0f + t);
}
__device__ __forceinline__ uint32_t smem_u32(const void* p) {
    return (uint32_t)__cvta_generic_to_shared(p);
}
__device__ __forceinline__ void cp_async16(uint32_t dst, const void* src) {
    asm volatile("cp.async.cg.shared.global [%0], [%1], 16;\n" :: "r"(dst), "l"(src));
}
__device__ __forceinline__ void cp_commit() { asm volatile("cp.async.commit_group;\n"); }
__device__ __forceinline__ void cp_wait0() { asm volatile("cp.async.wait_group 0;\n"); }
__device__ __forceinline__ void cp_wait1() { asm volatile("cp.async.wait_group 1;\n"); }

__device__ __forceinline__ void mma_f16(float c[4], const uint32_t a[4],
                                        uint32_t b0, uint32_t b1) {
    asm volatile(
        "mma.sync.aligned.m16n8k16.row.col.f32.f16.f16.f32 "
        "{%0,%1,%2,%3}, {%4,%5,%6,%7}, {%8,%9}, {%0,%1,%2,%3};"
        : "+f"(c[0]), "+f"(c[1]), "+f"(c[2]), "+f"(c[3])
        : "r"(a[0]), "r"(a[1]), "r"(a[2]), "r"(a[3]), "r"(b0), "r"(b1));
}

#define LDM_X4(r0, r1, r2, r3, addr) \
    asm volatile("ldmatrix.sync.aligned.m8n8.x4.shared.b16 {%0,%1,%2,%3}, [%4];" \
                 : "=r"(r0), "=r"(r1), "=r"(r2), "=r"(r3) : "r"(addr))
#define LDM_X4T(r0, r1, r2, r3, addr) \
    asm volatile("ldmatrix.sync.aligned.m8n8.x4.trans.shared.b16 {%0,%1,%2,%3}, [%4];" \
                 : "=r"(r0), "=r"(r1), "=r"(r2), "=r"(r3) : "r"(addr))

// ---------------------------------------------------------------------------
// Kernel 1: S4D kernel materialization (fp32 k)
// ---------------------------------------------------------------------------
__global__ __launch_bounds__(256) void k_kernel(
    const float* __restrict__ log_dt, const float* __restrict__ A_real_log,
    const float* __restrict__ A_imag, const float* __restrict__ C_re,
    const float* __restrict__ C_im) {
    int h = blockIdx.x;
    __shared__ float sCr[NN], sCi[NN], sAr[NN], sAi[NN];
    int tid = threadIdx.x;
    if (tid < NN) {
        float dt = expf(log_dt[h]);
        float Ar = -expf(A_real_log[h * NN + tid]);
        float Ai = A_imag[h * NN + tid];
        float dAr = Ar * dt, dAi = Ai * dt;
        float er = expf(dAr), sv, cv;
        sincosf(dAi, &sv, &cv);
        float Exr = er * cv - 1.0f;
        float Exi = er * sv;
        float cr = C_re[h * NN + tid], ci = C_im[h * NN + tid];
        float nr = cr * Exr - ci * Exi;
        float ni = cr * Exi + ci * Exr;
        float den = 1.0f / (Ar * Ar + Ai * Ai);
        sCr[tid] = (nr * Ar + ni * Ai) * den;
        sCi[tid] = (ni * Ar - nr * Ai) * den;
        sAr[tid] = dAr;
        sAi[tid] = dAi;
    }
    __syncthreads();
    float l = (float)tid;
    float acc = 0.0f;
#pragma unroll 4
    for (int n = 0; n < NN; n++) {
        float mag = expf(sAr[n] * l);
        float sv, cv;
        sincosf(sAi[n] * l, &sv, &cv);
        acc += sCr[n] * (mag * cv) - sCi[n] * (mag * sv);
    }
    g_k[h * LL + tid] = 2.0f * acc;
}

// ---------------------------------------------------------------------------
// Kernel 2: fp16-cast W (row-major)
// ---------------------------------------------------------------------------
__global__ __launch_bounds__(256) void wprep_kernel(const float* __restrict__ W) {
    int i = (blockIdx.x * 256 + threadIdx.x) * 4;
    if (i >= 2 * HH * HH) return;
    float4 v = *(const float4*)&W[i];
    union { __half2 h[2]; uint2 u; } c;
    c.h[0] = __floats2half2_rn(v.x, v.y);
    c.h[1] = __floats2half2_rn(v.z, v.w);
    *(uint2*)&g_Wh[i] = c.u;
}

// ---------------------------------------------------------------------------
// Kernel 2b: fp16-cast x
// ---------------------------------------------------------------------------
__global__ __launch_bounds__(256) void xprep_kernel(const float* __restrict__ x) {
    size_t i = ((size_t)blockIdx.x * 256 + threadIdx.x) * 4;
    float4 v = *(const float4*)&x[i];
    union { __half2 h[2]; uint2 u; } c;
    c.h[0] = __floats2half2_rn(v.x, v.y);
    c.h[1] = __floats2half2_rn(v.z, v.w);
    *(uint2*)&g_xh[i] = c.u;
}

// ---------------------------------------------------------------------------
// Kernel 3: conv as per-head Toeplitz GEMM (tensor cores).
// Y[b][l] = sum_s X[b][s] * T[s][l],  T[s][l] = k_h[l-s] (l>=s else 0)
// Block = (mb in 0..1, head h): M=64 batches, N=256 l, K=256 s in 16 chunks.
// 8 warps = 2(m) x 4(n); warp tile m32 x n64.
// T generated on the fly into smem fp16 (double-buffered); X via cp.async.
// Causal skip: warp wn computes chunk k0 only if wn*64+63 >= k0.
// Epilogue: + D*x, gelu, fp16 store to g_yh.  NOTE: mma rows are BATCHES,
// so the +8-row accumulator registers map to batch+8 (stride 8*HH*LL).
// ---------------------------------------------------------------------------
#define XP 24          // X tile pitch (halfs)
#define TP 264         // T tile pitch (halfs)

__global__ __launch_bounds__(256) void convgemm_kernel(const float* __restrict__ D) {
    __shared__ __half kh[256];
    __shared__ __align__(16) __half Xs[2][64 * XP];     // 6144 B
    __shared__ __align__(16) __half Ts[2][16 * TP];     // 16896 B

    int mb = blockIdx.x;            // 0..1 (64 batches each)
    int h  = blockIdx.y;
    int tid = threadIdx.x;
    int lane = tid & 31;
    int wid = tid >> 5;
    int wm = wid & 1;               // m: 32 rows
    int wn = wid >> 1;              // n: 64 cols

    // kernel row -> fp16 smem
    kh[tid] = __float2half(g_k[(size_t)h * LL + tid]);

    float acc[2][8][4];
#pragma unroll
    for (int mi = 0; mi < 2; mi++)
#pragma unroll
        for (int t = 0; t < 8; t++)
#pragma unroll
            for (int r = 0; r < 4; r++) acc[mi][t][r] = 0.0f;

    // X staging: threads 0..127 -> (row, seg)
    int xr = tid >> 1, xseg = tid & 1;
    const __half* xS = g_xh + ((size_t)(mb * 64 + xr) * HH + h) * LL + xseg * 8;  // += 16/chunk
    uint32_t xD[2] = { smem_u32(&Xs[0][xr * XP + xseg * 8]),
                       smem_u32(&Xs[1][xr * XP + xseg * 8]) };

    // T generation mapping: si = tid>>4 (s within chunk), l0 = (tid&15)*16
    int si = tid >> 4;
    int l0g = (tid & 15) * 16;

    // fragment addresses
    int lm = lane & 15, lh = lane >> 4;
    uint32_t xAddr[2] = { smem_u32(&Xs[0][(wm * 32 + lm) * XP + lh * 8]),
                          smem_u32(&Xs[1][(wm * 32 + lm) * XP + lh * 8]) };
    uint32_t tAddr[2] = { smem_u32(&Ts[0][lm * TP + wn * 64 + lh * 8]),
                          smem_u32(&Ts[1][lm * TP + wn * 64 + lh * 8]) };

#define GEN_T(buf, k0) do { \
        int sg = (k0) + si; \
        int lbase = (k0) & ~63; \
        if (l0g + 15 >= lbase) { \
            _Pragma("unroll") \
            for (int j = 0; j < 8; j++) { \
                int l = l0g + 2 * j; \
                __half v0 = (l >= sg)     ? kh[l - sg]     : __half(0.0f); \
                __half v1 = (l + 1 >= sg) ? kh[l + 1 - sg] : __half(0.0f); \
                *(__half2*)&Ts[buf][si * TP + l] = __halves2half2(v0, v1); \
            } \
        } } while (0)

#define STAGE_X(buf) do { \
        if (tid < 128) cp_async16(xD[buf], xS); \
        cp_commit(); xS += 16; } while (0)

#define CONV_COMPUTE(buf, k0) do { \
        if (wn * 64 + 63 >= (k0)) { \
            uint32_t aa0[4], aa1[4]; \
            LDM_X4(aa0[0], aa0[1], aa0[2], aa0[3], xAddr[buf]); \
            LDM_X4(aa1[0], aa1[1], aa1[2], aa1[3], xAddr[buf] + 16 * XP * 2); \
            _Pragma("unroll") \
            for (int p = 0; p < 4; p++) { \
                if (wn * 64 + p * 16 + 15 >= (k0)) { \
                    uint32_t b0, b1, b2, b3; \
                    LDM_X4T(b0, b1, b2, b3, tAddr[buf] + p * 32); \
                    mma_f16(acc[0][2 * p],     aa0, b0, b1); \
                    mma_f16(acc[0][2 * p + 1], aa0, b2, b3); \
                    mma_f16(acc[1][2 * p],     aa1, b0, b1); \
                    mma_f16(acc[1][2 * p + 1], aa1, b2, b3); \
                } \
            } \
        } } while (0)

    // prologue: chunk 0 -> buf0  (GEN_T reads kh written above: barrier first)
    __syncthreads();
    GEN_T(0, 0);
    STAGE_X(0);
    cp_wait0();
    __syncthreads();

#pragma unroll 1
    for (int c = 0; c < 16; c++) {
        int cur = c & 1, nxt = cur ^ 1;
        if (c < 15) {
            GEN_T(nxt, (c + 1) * 16);
            STAGE_X(nxt);
        }
        CONV_COMPUTE(cur, c * 16);
        if (c < 15) cp_wait0();
        __syncthreads();
    }

    // epilogue: + D*x, gelu, store fp16.  batch stride = HH*LL!
    float Dv = D[h];
    int r = lane >> 2;
    int c2 = (lane & 3) << 1;
    const size_t BSTRIDE8 = (size_t)8 * HH * LL;
#pragma unroll
    for (int mi = 0; mi < 2; mi++) {
        int row0 = mb * 64 + wm * 32 + mi * 16 + r;      // batch index
#pragma unroll
        for (int t = 0; t < 8; t++) {
            int l = wn * 64 + t * 8 + c2;
            size_t a0 = ((size_t)row0 * HH + h) * LL + l;
            size_t a8 = a0 + BSTRIDE8;                   // batch row0+8
            __half2 x0 = *(const __half2*)&g_xh[a0];
            __half2 x8 = *(const __half2*)&g_xh[a8];
            float y0 = gelu_tanh(acc[mi][t][0] + Dv * __low2float(x0));
            float y1 = gelu_tanh(acc[mi][t][1] + Dv * __high2float(x0));
            float y2 = gelu_tanh(acc[mi][t][2] + Dv * __low2float(x8));
            float y3 = gelu_tanh(acc[mi][t][3] + Dv * __high2float(x8));
            *(__half2*)&g_yh[a0] = __floats2half2_rn(y0, y1);
            *(__half2*)&g_yh[a8] = __floats2half2_rn(y2, y3);
        }
    }
}

// ---------------------------------------------------------------------------
// Kernel 4: fp16 GEMM + GLU (mma.sync m16n8k16 + ldmatrix), 3-stage cp.async
// pipeline with wait_group 1 (one barrier per k32 chunk).
// Block: 64 h-out (both GLU halves) x 128 l; 8 warps = 4(m) x 2(n).
// ---------------------------------------------------------------------------
#define AP 40
#define BP 136
#define A_H (128 * AP)                 // 5120 halfs
#define B_H (32 * BP)                  // 4352 halfs
#define ST_H (A_H + B_H)               // 9472 halfs
#define ST_B (ST_H * 2)                // 18944 B / stage
#define GEMM_SMEM_BYTES (3 * ST_B)     // 56832 B

__global__ __launch_bounds__(256, 2) void gemm_glu_kernel(const float* __restrict__ bias,
                                                          float* __restrict__ out) {
    extern __shared__ __half smh[];

    int lblk = blockIdx.x;
    int hb   = blockIdx.y;
    int b    = blockIdx.z;
    int tid = threadIdx.x;
    int lane = tid & 31;
    int wid = tid >> 5;
    int wm = wid & 3;
    int wn = wid >> 2;

    float ca[8][4], cb[8][4];
#pragma unroll
    for (int t = 0; t < 8; t++)
#pragma unroll
        for (int r = 0; r < 4; r++) { ca[t][r] = 0.0f; cb[t][r] = 0.0f; }

    // staging descriptors
    int arow = tid >> 1, aseg2 = (tid & 1) * 2;
    int wrow = (arow < 64) ? (hb * 64 + arow) : (960 + hb * 64 + arow);
    const __half* aS = g_Wh + (size_t)wrow * HH + aseg2 * 8;
    uint32_t aD = smem_u32(smh + arow * AP + aseg2 * 8);

    int brow = tid >> 3, bs2 = (tid & 7) * 2;
    const __half* bS = g_yh + (size_t)b * HH * LL + (size_t)brow * LL + lblk * 128 + bs2 * 8;
    uint32_t bD = smem_u32(smh + A_H + brow * BP + bs2 * 8);

#define STAGE(off) do { \
        cp_async16(aD + (off), aS); cp_async16(aD + (off) + 16, aS + 8); \
        cp_async16(bD + (off), bS); cp_async16(bD + (off) + 16, bS + 8); \
        cp_commit(); aS += 32; bS += 32 * LL; } while (0)

    int lm = lane & 15, lh = lane >> 4;
    uint32_t aAddrA = smem_u32(smh + (wm * 16 + lm) * AP + lh * 8);
    uint32_t aAddrB = aAddrA + 64 * AP * 2;
    uint32_t bAddr  = smem_u32(smh + A_H + lm * BP + wn * 64 + lh * 8);

#define COMPUTE(off) do { \
        _Pragma("unroll") \
        for (int s = 0; s < 2; s++) { \
            uint32_t aa[4], ab[4]; \
            LDM_X4(aa[0], aa[1], aa[2], aa[3], aAddrA + (off) + s * 32); \
            LDM_X4(ab[0], ab[1], ab[2], ab[3], aAddrB + (off) + s * 32); \
            _Pragma("unroll") \
            for (int p = 0; p < 4; p++) { \
                uint32_t b0, b1, b2, b3; \
                LDM_X4T(b0, b1, b2, b3, bAddr + (off) + s * (16 * BP * 2) + p * 32); \
                mma_f16(ca[2 * p],     aa, b0, b1); \
                mma_f16(ca[2 * p + 1], aa, b2, b3); \
                mma_f16(cb[2 * p],     ab, b0, b1); \
                mma_f16(cb[2 * p + 1], ab, b2, b3); \
            } \
        } } while (0)

    // 3-stage pipeline over 32 chunks
    STAGE(0);
    STAGE(ST_B);
    uint32_t offC = 0, offS = 2 * ST_B;

#pragma unroll 1
    for (int i = 0; i < 32; i++) {
        if (i < 31) cp_wait1(); else cp_wait0();
        __syncthreads();
        if (i < 30) STAGE(offS);
        COMPUTE(offC);
        offC += ST_B; if (offC == 3 * ST_B) offC = 0;
        offS += ST_B; if (offS == 3 * ST_B) offS = 0;
    }

    // epilogue: bias + GLU
    int r = lane >> 2;
    int c2 = (lane & 3) << 1;
    int h = hb * 64 + wm * 16 + r;
    float ba0 = bias[h],     bb0 = bias[h + HH];
    float ba8 = bias[h + 8], bb8 = bias[h + 8 + HH];
    size_t ob0 = ((size_t)b * HH + h) * LL;
    size_t ob8 = ob0 + (size_t)8 * LL;
#pragma unroll
    for (int t = 0; t < 8; t++) {
        int ll = lblk * 128 + wn * 64 + t * 8 + c2;
        float av, bv;
        float2 w0, w8;
        av = ca[t][0] + ba0; bv = cb[t][0] + bb0;
        w0.x = av * (1.0f / (1.0f + expf(-bv)));
        av = ca[t][1] + ba0; bv = cb[t][1] + bb0;
        w0.y = av * (1.0f / (1.0f + expf(-bv)));
        av = ca[t][2] + ba8; bv = cb[t][2] + bb8;
        w8.x = av * (1.0f / (1.0f + expf(-bv)));
        av = ca[t][3] + ba8; bv = cb[t][3] + bb8;
        w8.y = av * (1.0f / (1.0f + expf(-bv)));
        *(float2*)&out[ob0 + ll] = w0;
        *(float2*)&out[ob8 + ll] = w8;
    }
}

// ---------------------------------------------------------------------------
extern "C" void kernel_launch(void* const* d_in, const int* in_sizes, int n_in,
                              void* d_out, int out_size) {
    const float* x          = (const float*)d_in[0];
    const float* log_dt     = (const float*)d_in[1];
    const float* A_real_log = (const float*)d_in[2];
    const float* A_imag     = (const float*)d_in[3];
    const float* C_re       = (const float*)d_in[4];
    const float* C_im       = (const float*)d_in[5];
    const float* D          = (const float*)d_in[6];
    const float* W_out      = (const float*)d_in[7];
    const float* b_out      = (const float*)d_in[8];
    float* out = (float*)d_out;

    cudaFuncSetAttribute(gemm_glu_kernel, cudaFuncAttributeMaxDynamicSharedMemorySize,
                         GEMM_SMEM_BYTES);

    k_kernel<<<HH, 256>>>(log_dt, A_real_log, A_imag, C_re, C_im);
    wprep_kernel<<<(2 * HH * HH) / 1024, 256>>>(W_out);
    xprep_kernel<<<(int)(((size_t)BB * HH * LL) / 1024), 256>>>(x);
    convgemm_kernel<<<dim3(2, HH), 256>>>(D);
    gemm_glu_kernel<<<dim3(2, 16, BB), 256, GEMM_SMEM_BYTES>>>(b_out, out);
}